// round 7
// baseline (speedup 1.0000x reference)
#include <cuda_runtime.h>

// Depthwise 3x3 conv with hard-one-hot kernel == pure spatial shift, zero pad:
//   out[b,c,h,w] = x[b,c, h+dy, w+dx],  (dy,dx) = argmax(|weight|) - 1
//
// One warp per image row, ONE 256-bit access per lane each way
// (sm_10x ld/st.global.v8.f32; lane covers cols 8l..8l+7, 32B-aligned).
// Horizontal +-1 shift fixed by a single register shuffle; the value shuffled
// past lane 0/31 is exactly the zero padding. Argmax once per block via smem.

__global__ __launch_bounds__(256) void shift_row_v8_kernel(
    const float* __restrict__ x, const float* __restrict__ w9,
    float* __restrict__ out)
{
    __shared__ int2 s_shift;
    if (threadIdx.x == 0) {
        float best = -1.0f;
        int bi = 0;
        #pragma unroll
        for (int i = 0; i < 9; ++i) {
            float a = fabsf(w9[i]);
            if (a > best) { best = a; bi = i; }   // first occurrence wins (jnp.argmax)
        }
        s_shift = make_int2(bi / 3 - 1, bi % 3 - 1);
    }
    __syncthreads();
    const int dy = s_shift.x;
    const int dx = s_shift.y;

    const int gw   = (blockIdx.x * blockDim.x + threadIdx.x) >> 5;  // row id
    const int lane = threadIdx.x & 31;

    const int h  = gw & 255;                   // row within plane
    const int sh = h + dy;
    const size_t plane = (size_t)(gw >> 8);    // fused b*c plane

    float o0, o1, o2, o3, o4, o5, o6, o7;
    if ((unsigned)sh < 256u) {                 // warp-uniform
        const float* src = x + ((plane << 8) + (size_t)sh) * 256 + (lane << 3);
        float a0, a1, a2, a3, a4, a5, a6, a7;
        asm volatile("ld.global.nc.v8.f32 {%0,%1,%2,%3,%4,%5,%6,%7}, [%8];"
                     : "=f"(a0), "=f"(a1), "=f"(a2), "=f"(a3),
                       "=f"(a4), "=f"(a5), "=f"(a6), "=f"(a7)
                     : "l"(src));
        if (dx == 0) {
            o0 = a0; o1 = a1; o2 = a2; o3 = a3;
            o4 = a4; o5 = a5; o6 = a6; o7 = a7;
        } else if (dx > 0) {
            float nxt = __shfl_down_sync(0xffffffffu, a0, 1);
            if (lane == 31) nxt = 0.0f;        // col 256 -> zero pad
            o0 = a1; o1 = a2; o2 = a3; o3 = a4;
            o4 = a5; o5 = a6; o6 = a7; o7 = nxt;
        } else {
            float prv = __shfl_up_sync(0xffffffffu, a7, 1);
            if (lane == 0) prv = 0.0f;         // col -1 -> zero pad
            o0 = prv; o1 = a0; o2 = a1; o3 = a2;
            o4 = a3; o5 = a4; o6 = a5; o7 = a6;
        }
    } else {
        o0 = o1 = o2 = o3 = o4 = o5 = o6 = o7 = 0.0f;
    }

    float* dst = out + ((size_t)gw << 8) + (lane << 3);
    asm volatile("st.global.v8.f32 [%0], {%1,%2,%3,%4,%5,%6,%7,%8};"
                 :: "l"(dst),
                    "f"(o0), "f"(o1), "f"(o2), "f"(o3),
                    "f"(o4), "f"(o5), "f"(o6), "f"(o7)
                 : "memory");
}

extern "C" void kernel_launch(void* const* d_in, const int* in_sizes, int n_in,
                              void* d_out, int out_size) {
    const float* x = (const float*)d_in[0];
    const float* w = (const float*)d_in[1];
    float* out = (float*)d_out;

    int nrows  = out_size >> 8;     // 262144 rows
    int blocks = nrows >> 3;        // 8 warps (rows) per 256-thread block
    shift_row_v8_kernel<<<blocks, 256>>>(x, w, out);
}